// round 13
// baseline (speedup 1.0000x reference)
#include <cuda_runtime.h>
#include <math.h>
#include <stdint.h>

#define D 256
#define O 10
#define NS 64
#define R 640   // NS*O

// ---------------- scratch ----------------
__device__ float d_W2P[D * D];     // float4 at (k4*D + t) holds W2[t][4k4..4k4+3]
__device__ float d_H1[2 * NS * D];
__device__ float d_H2[2 * NS * D];
__device__ float d_G1[2 * R * D];
__device__ float d_G2[2 * R * D];
__device__ float d_C[3][NS * NS];

// ---------------- tf32 helpers ----------------
__device__ __forceinline__ uint32_t f2tf32(float f) {
    uint32_t r;
    asm("cvt.rna.tf32.f32 %0, %1;" : "=r"(r) : "f"(f));
    return r;
}
__device__ __forceinline__ void mma_tf32(
    float& c0, float& c1, float& c2, float& c3,
    uint32_t a0, uint32_t a1, uint32_t a2, uint32_t a3,
    uint32_t b0, uint32_t b1)
{
    asm volatile(
        "mma.sync.aligned.m16n8k8.row.col.f32.tf32.tf32.f32 "
        "{%0,%1,%2,%3}, {%4,%5,%6,%7}, {%8,%9}, {%0,%1,%2,%3};"
        : "+f"(c0), "+f"(c1), "+f"(c2), "+f"(c3)
        : "r"(a0), "r"(a1), "r"(a2), "r"(a3), "r"(b0), "r"(b1));
}

// ================= K1: W2 pack (blocks 0..63) + fused forward, 4 samples/CTA =====
// Register-double-buffered 16-wide W batches; each weight feeds 4 sample chains
// (8 independent accumulator chains). launch_bounds(256,1) lifts the reg cap.
__global__ __launch_bounds__(256, 1) void k1_fwd(
    const float* __restrict__ x1, const float* __restrict__ x2,
    const float* __restrict__ W1, const float* __restrict__ b1,
    const float* __restrict__ W2, const float* __restrict__ b2,
    const float* __restrict__ W3)
{
    __shared__ __align__(16) float4 xT[D];
    __shared__ __align__(16) float4 h1T[D];

    const int b = blockIdx.x, t = threadIdx.x;

    if (b < 64) {
        int gid = b * 256 + t;
        int k4 = gid & 63, tw = gid >> 6;
        float4 v = *(const float4*)&W2[tw * D + k4 * 4];
        *(float4*)&d_W2P[(k4 * D + tw) * 4] = v;
        return;
    }

    const int s0 = (b - 64) * 4;
    {
        float4 xv;
        const float* xr;
        float tmp[4];
#pragma unroll
        for (int s = 0; s < 4; s++) {
            int sg = s0 + s;
            xr = (sg < NS) ? (x1 + sg * D) : (x2 + (sg - NS) * D);
            tmp[s] = xr[t];
        }
        xv = make_float4(tmp[0], tmp[1], tmp[2], tmp[3]);
        xT[t] = xv;
    }
    __syncthreads();

    float w0[16], w1[16];

#define K1_FMA4(ACC, XV, W) {                                                  \
    ACC[0] += (XV).x * (W); ACC[1] += (XV).y * (W);                            \
    ACC[2] += (XV).z * (W); ACC[3] += (XV).w * (W); }

#define K1_LAYER(Wp, SRC, AE, AO)                                              \
    _Pragma("unroll")                                                          \
    for (int j = 0; j < 16; j++) w0[j] = (Wp)[j * D + t];                      \
    _Pragma("unroll 1")                                                        \
    for (int ib = 0; ib < D; ib += 32) {                                       \
        _Pragma("unroll")                                                      \
        for (int j = 0; j < 16; j++) w1[j] = (Wp)[(ib + 16 + j) * D + t];      \
        _Pragma("unroll")                                                      \
        for (int j = 0; j < 16; j += 2) {                                      \
            float4 xa = SRC[ib + j], xb = SRC[ib + j + 1];                     \
            K1_FMA4(AE, xa, w0[j])                                             \
            K1_FMA4(AO, xb, w0[j + 1])                                         \
        }                                                                      \
        if (ib + 32 < D) {                                                     \
            _Pragma("unroll")                                                  \
            for (int j = 0; j < 16; j++) w0[j] = (Wp)[(ib + 32 + j) * D + t];  \
        }                                                                      \
        _Pragma("unroll")                                                      \
        for (int j = 0; j < 16; j += 2) {                                      \
            float4 xa = SRC[ib + 16 + j], xb = SRC[ib + 16 + j + 1];           \
            K1_FMA4(AE, xa, w1[j])                                             \
            K1_FMA4(AO, xb, w1[j + 1])                                         \
        }                                                                      \
    }

    // ---- layer 1 ----
    float bias = b1[t];
    float ae[4] = {bias, bias, bias, bias};
    float ao[4] = {0.f, 0.f, 0.f, 0.f};
    K1_LAYER(W1, xT, ae, ao)
    float h1v[4];
#pragma unroll
    for (int s = 0; s < 4; s++) {
        h1v[s] = tanhf(ae[s] + ao[s]);
        d_H1[(s0 + s) * D + t] = h1v[s];
    }
    h1T[t] = make_float4(h1v[0], h1v[1], h1v[2], h1v[3]);
    __syncthreads();

    // ---- layer 2 ----
    bias = b2[t];
#pragma unroll
    for (int s = 0; s < 4; s++) { ae[s] = bias; ao[s] = 0.f; }
    K1_LAYER(W2, h1T, ae, ao)
    float t2[4];
#pragma unroll
    for (int s = 0; s < 4; s++) {
        float h2 = tanhf(ae[s] + ao[s]);
        d_H2[(s0 + s) * D + t] = h2;
        t2[s] = 1.f - h2 * h2;
    }

    // ---- G2[s,a,t] = W3[t,a] * (1 - h2^2) ----
#pragma unroll
    for (int a = 0; a < O; a++) {
        float w3 = W3[t * O + a];
#pragma unroll
        for (int s = 0; s < 4; s++)
            d_G2[((s0 + s) * O + a) * D + t] = w3 * t2[s];
    }
#undef K1_LAYER
#undef K1_FMA4
}

// ======== kC: G1 backward (blocks 0..255) + pairwise dots (256..319) ==============
__global__ __launch_bounds__(256) void kC_bwd_dots(
    const float* __restrict__ x1, const float* __restrict__ x2)
{
    __shared__ float sm[5 * D];
    const int b = blockIdx.x, t = threadIdx.x;

    if (b < 256) {
        const int s = b >> 1, half = b & 1;
#pragma unroll
        for (int j = 0; j < 5; j++)
            sm[j * D + t] = d_G2[(s * O + half * 5 + j) * D + t];
        float h1 = d_H1[s * D + t];
        float t1 = 1.0f - h1 * h1;
        __syncthreads();

        float a0 = 0.f, a1 = 0.f, a2 = 0.f, a3 = 0.f, a4 = 0.f;
#pragma unroll 4
        for (int k4 = 0; k4 < 64; k4++) {
            float4 w  = *(const float4*)&d_W2P[(k4 * D + t) * 4];
            float4 g0 = *(const float4*)&sm[0 * D + k4 * 4];
            float4 g1 = *(const float4*)&sm[1 * D + k4 * 4];
            float4 g2 = *(const float4*)&sm[2 * D + k4 * 4];
            float4 g3 = *(const float4*)&sm[3 * D + k4 * 4];
            float4 g4 = *(const float4*)&sm[4 * D + k4 * 4];
            a0 += w.x * g0.x + w.y * g0.y + w.z * g0.z + w.w * g0.w;
            a1 += w.x * g1.x + w.y * g1.y + w.z * g1.z + w.w * g1.w;
            a2 += w.x * g2.x + w.y * g2.y + w.z * g2.z + w.w * g2.w;
            a3 += w.x * g3.x + w.y * g3.y + w.z * g3.z + w.w * g3.w;
            a4 += w.x * g4.x + w.y * g4.y + w.z * g4.z + w.w * g4.w;
        }
        const int base = (s * O + half * 5) * D + t;
        d_G1[base + 0 * D] = t1 * a0;
        d_G1[base + 1 * D] = t1 * a1;
        d_G1[base + 2 * D] = t1 * a2;
        d_G1[base + 3 * D] = t1 * a3;
        d_G1[base + 4 * D] = t1 * a4;
        return;
    }

    const int n = b - 256;
    float* xa  = sm;
    float* h1a = sm + D;
    float* h2a = sm + 2 * D;
    xa[t]  = x1[n * D + t];
    h1a[t] = d_H1[n * D + t];
    h2a[t] = d_H2[n * D + t];
    __syncthreads();

    const int warp = t >> 5, lane = t & 31;
#pragma unroll
    for (int mi = 0; mi < 8; mi++) {
        int m = warp * 8 + mi;
        const float* x2r = x2 + m * D;
        const float* h1r = d_H1 + (NS + m) * D;
        const float* h2r = d_H2 + (NS + m) * D;
        float s0 = 0.f, s1 = 0.f, s2 = 0.f;
#pragma unroll
        for (int k = lane; k < D; k += 32) {
            s0 += xa[k]  * x2r[k];
            s1 += h1a[k] * h1r[k];
            s2 += h2a[k] * h2r[k];
        }
#pragma unroll
        for (int off = 16; off > 0; off >>= 1) {
            s0 += __shfl_down_sync(0xffffffffu, s0, off);
            s1 += __shfl_down_sync(0xffffffffu, s1, off);
            s2 += __shfl_down_sync(0xffffffffu, s2, off);
        }
        if (lane == 0) {
            d_C[0][n * NS + m] = s0 + 1.0f;
            d_C[1][n * NS + m] = s1 + 1.0f;
            d_C[2][n * NS + m] = s2 + 1.0f;
        }
    }
}

// ======== kP: tensor-core pair-GEMMs (3xTF32, both layers) + fused NTK combine ====
// 64x64 tile, 512 thr (16 warps), 16 flattened stages (8 per layer), software-
// pipelined: stage st+1's LDGs issue between syncs, overlapping stage st's MMAs.
__global__ __launch_bounds__(512) void kP_pair(float* __restrict__ out)
{
    __shared__ float sAhi[64][36];
    __shared__ float sAlo[64][36];
    __shared__ float sBhi[64][36];
    __shared__ float sBlo[64][36];

    const int tid  = threadIdx.x;
    const int lane = tid & 31;
    const int w    = tid >> 5;      // 0..15
    const int g    = lane >> 2;
    const int t4   = lane & 3;
    const int rt   = w & 3;
    const int cq   = w >> 2;        // 0..3
    const int r0 = blockIdx.y * 64, c0 = blockIdx.x * 64;

    float acc_h[2][2][4];
    float acc_c[2][2][4];
#pragma unroll
    for (int l = 0; l < 2; l++)
#pragma unroll
        for (int nt = 0; nt < 2; nt++)
#pragma unroll
            for (int q = 0; q < 4; q++) { acc_h[l][nt][q] = 0.f; acc_c[l][nt][q] = 0.f; }

    const int srow = tid >> 3;           // 0..63
    const int sq   = (tid & 7) * 4;      // 0..28

#define KP_LDG(st) {                                                           \
    const float* G = ((st) < 8) ? d_G1 : d_G2;                                 \
    const int kc = ((st) & 7) * 32;                                            \
    va = *(const float4*)&G[(r0 + srow) * D + kc + sq];                        \
    vb = *(const float4*)&G[(R + c0 + srow) * D + kc + sq];                    \
}

#define KP_MMA(LI) {                                                           \
    _Pragma("unroll")                                                          \
    for (int kk = 0; kk < 4; kk++) {                                           \
        const int kb = kk * 8 + t4;                                            \
        const int ar = rt * 16 + g;                                            \
        uint32_t ah0 = __float_as_uint(sAhi[ar][kb]);                          \
        uint32_t ah1 = __float_as_uint(sAhi[ar + 8][kb]);                      \
        uint32_t ah2 = __float_as_uint(sAhi[ar][kb + 4]);                      \
        uint32_t ah3 = __float_as_uint(sAhi[ar + 8][kb + 4]);                  \
        uint32_t al0 = __float_as_uint(sAlo[ar][kb]);                          \
        uint32_t al1 = __float_as_uint(sAlo[ar + 8][kb]);                      \
        uint32_t al2 = __float_as_uint(sAlo[ar][kb + 4]);                      \
        uint32_t al3 = __float_as_uint(sAlo[ar + 8][kb + 4]);                  \
        _Pragma("unroll")                                                      \
        for (int nt = 0; nt < 2; nt++) {                                       \
            const int nb = cq * 16 + nt * 8 + g;                               \
            uint32_t bh0 = __float_as_uint(sBhi[nb][kb]);                      \
            uint32_t bh1 = __float_as_uint(sBhi[nb][kb + 4]);                  \
            uint32_t bl0 = __float_as_uint(sBlo[nb][kb]);                      \
            uint32_t bl1 = __float_as_uint(sBlo[nb][kb + 4]);                  \
            float* chh = acc_h[LI][nt];                                        \
            float* ccr = acc_c[LI][nt];                                        \
            mma_tf32(chh[0], chh[1], chh[2], chh[3], ah0, ah1, ah2, ah3, bh0, bh1); \
            mma_tf32(ccr[0], ccr[1], ccr[2], ccr[3], ah0, ah1, ah2, ah3, bl0, bl1); \
            mma_tf32(ccr[0], ccr[1], ccr[2], ccr[3], al0, al1, al2, al3, bh0, bh1); \
        }                                                                      \
    } }

    float4 va, vb;
    KP_LDG(0)

#pragma unroll 1
    for (int st = 0; st < 16; st++) {
        // split current stage's registers and stage to smem
        {
            float av[4] = {va.x, va.y, va.z, va.w};
            float bv[4] = {vb.x, vb.y, vb.z, vb.w};
            float ah[4], al[4], bh[4], bl[4];
#pragma unroll
            for (int j = 0; j < 4; j++) {
                uint32_t h = f2tf32(av[j]);
                ah[j] = __uint_as_float(h);
                al[j] = __uint_as_float(f2tf32(av[j] - ah[j]));
                h = f2tf32(bv[j]);
                bh[j] = __uint_as_float(h);
                bl[j] = __uint_as_float(f2tf32(bv[j] - bh[j]));
            }
            *(float4*)&sAhi[srow][sq] = make_float4(ah[0], ah[1], ah[2], ah[3]);
            *(float4*)&sAlo[srow][sq] = make_float4(al[0], al[1], al[2], al[3]);
            *(float4*)&sBhi[srow][sq] = make_float4(bh[0], bh[1], bh[2], bh[3]);
            *(float4*)&sBlo[srow][sq] = make_float4(bl[0], bl[1], bl[2], bl[3]);
        }
        __syncthreads();

        if (st < 15) KP_LDG(st + 1)      // in flight during MMAs

        if (st < 8) { KP_MMA(0) } else { KP_MMA(1) }
        __syncthreads();                  // smem consumed; safe to overwrite
    }
#undef KP_LDG
#undef KP_MMA

    // ---- epilogue: out[n,m,a,b] = C0*P0 + C1*P1 + (a==b)*C2 ----
    const float* C0 = d_C[0];
    const float* C1 = d_C[1];
    const float* C2 = d_C[2];
#pragma unroll
    for (int nt = 0; nt < 2; nt++) {
        int col = c0 + cq * 16 + nt * 8 + 2 * t4;
        int m0 = col / 10,       bb0 = col - m0 * 10;
        int m1 = (col + 1) / 10, bb1 = (col + 1) - m1 * 10;
#pragma unroll
        for (int half = 0; half < 2; half++) {
            int row = r0 + rt * 16 + g + half * 8;
            int n = row / 10, a = row - n * 10;
            int ci0 = n * NS + m0, ci1 = n * NS + m1;
            float p00 = acc_h[0][nt][half * 2 + 0] + acc_c[0][nt][half * 2 + 0];
            float p10 = acc_h[1][nt][half * 2 + 0] + acc_c[1][nt][half * 2 + 0];
            float p01 = acc_h[0][nt][half * 2 + 1] + acc_c[0][nt][half * 2 + 1];
            float p11 = acc_h[1][nt][half * 2 + 1] + acc_c[1][nt][half * 2 + 1];
            float v0 = C0[ci0] * p00 + C1[ci0] * p10;
            float v1 = C0[ci1] * p01 + C1[ci1] * p11;
            if (a == bb0) v0 += C2[ci0];
            if (a == bb1) v1 += C2[ci1];
            out[ci0 * 100 + a * 10 + bb0] = v0;
            out[ci1 * 100 + a * 10 + bb1] = v1;
        }
    }
}

// ---------------- launcher ----------------
extern "C" void kernel_launch(void* const* d_in, const int* in_sizes, int n_in,
                              void* d_out, int out_size) {
    const float* x1 = (const float*)d_in[0];
    const float* x2 = (const float*)d_in[1];
    const float* W1 = (const float*)d_in[2];
    const float* b1 = (const float*)d_in[3];
    const float* W2 = (const float*)d_in[4];
    const float* b2 = (const float*)d_in[5];
    const float* W3 = (const float*)d_in[6];
    float* out = (float*)d_out;

    k1_fwd<<<96, 256>>>(x1, x2, W1, b1, W2, b2, W3);
    kC_bwd_dots<<<320, 256>>>(x1, x2);
    kP_pair<<<dim3(10, 10), 512>>>(out);
}

// round 14
// speedup vs baseline: 1.0513x; 1.0513x over previous
#include <cuda_runtime.h>
#include <math.h>
#include <stdint.h>

#define D 256
#define O 10
#define NS 64
#define R 640   // NS*O

// ---------------- scratch ----------------
__device__ float d_W2P[D * D];     // float4 at (k4*D + t) holds W2[t][4k4..4k4+3]
__device__ float d_H1[2 * NS * D];
__device__ float d_H2[2 * NS * D];
__device__ float d_G1[2 * R * D];
__device__ float d_G2[2 * R * D];
__device__ float d_C[3][NS * NS];

// ---------------- tf32 helpers ----------------
__device__ __forceinline__ uint32_t f2tf32(float f) {
    uint32_t r;
    asm("cvt.rna.tf32.f32 %0, %1;" : "=r"(r) : "f"(f));
    return r;
}
__device__ __forceinline__ void mma_tf32(
    float& c0, float& c1, float& c2, float& c3,
    uint32_t a0, uint32_t a1, uint32_t a2, uint32_t a3,
    uint32_t b0, uint32_t b1)
{
    asm volatile(
        "mma.sync.aligned.m16n8k8.row.col.f32.tf32.tf32.f32 "
        "{%0,%1,%2,%3}, {%4,%5,%6,%7}, {%8,%9}, {%0,%1,%2,%3};"
        : "+f"(c0), "+f"(c1), "+f"(c2), "+f"(c3)
        : "r"(a0), "r"(a1), "r"(a2), "r"(a3), "r"(b0), "r"(b1));
}

// ================= K1: W2 pack (blocks 0..63) + fused forward, 2 samples/CTA =====
// R12 version (measured best): register-double-buffered 16-wide W load batches;
// launch_bounds(256,1) lifts the 32-reg cap so 16 LDGs stay in flight.
__global__ __launch_bounds__(256, 1) void k1_fwd(
    const float* __restrict__ x1, const float* __restrict__ x2,
    const float* __restrict__ W1, const float* __restrict__ b1,
    const float* __restrict__ W2, const float* __restrict__ b2,
    const float* __restrict__ W3)
{
    __shared__ __align__(8) float2 xT[D];
    __shared__ __align__(8) float2 h1T[D];

    const int b = blockIdx.x, t = threadIdx.x;

    if (b < 64) {
        int gid = b * 256 + t;
        int k4 = gid & 63, tw = gid >> 6;
        float4 v = *(const float4*)&W2[tw * D + k4 * 4];
        *(float4*)&d_W2P[(k4 * D + tw) * 4] = v;
        return;
    }

    const int s0 = (b - 64) * 2;
    const float* xr0 = (s0 < NS) ? (x1 + s0 * D) : (x2 + (s0 - NS) * D);
    const float* xr1 = (s0 + 1 < NS) ? (x1 + (s0 + 1) * D) : (x2 + (s0 + 1 - NS) * D);
    xT[t] = make_float2(xr0[t], xr1[t]);
    __syncthreads();

    float w0[16], w1[16];

#define K1_LAYER(Wp, SRC, A0, A1, C0, C1)                                      \
    _Pragma("unroll")                                                          \
    for (int j = 0; j < 16; j++) w0[j] = (Wp)[j * D + t];                      \
    _Pragma("unroll 1")                                                        \
    for (int ib = 0; ib < D; ib += 32) {                                       \
        _Pragma("unroll")                                                      \
        for (int j = 0; j < 16; j++) w1[j] = (Wp)[(ib + 16 + j) * D + t];      \
        _Pragma("unroll")                                                      \
        for (int j = 0; j < 16; j += 2) {                                      \
            float2 xa = SRC[ib + j], xb = SRC[ib + j + 1];                     \
            A0 += xa.x * w0[j];     C0 += xa.y * w0[j];                        \
            A1 += xb.x * w0[j + 1]; C1 += xb.y * w0[j + 1];                    \
        }                                                                      \
        if (ib + 32 < D) {                                                     \
            _Pragma("unroll")                                                  \
            for (int j = 0; j < 16; j++) w0[j] = (Wp)[(ib + 32 + j) * D + t];  \
        }                                                                      \
        _Pragma("unroll")                                                      \
        for (int j = 0; j < 16; j += 2) {                                      \
            float2 xa = SRC[ib + 16 + j], xb = SRC[ib + 16 + j + 1];           \
            A0 += xa.x * w1[j];     C0 += xa.y * w1[j];                        \
            A1 += xb.x * w1[j + 1]; C1 += xb.y * w1[j + 1];                    \
        }                                                                      \
    }

    // ---- layer 1 ----
    float bias = b1[t];
    float a0 = bias, a1 = 0.f, c0 = bias, c1 = 0.f;
    K1_LAYER(W1, xT, a0, a1, c0, c1)
    float h1_0 = tanhf(a0 + a1), h1_1 = tanhf(c0 + c1);
    d_H1[(s0 + 0) * D + t] = h1_0;
    d_H1[(s0 + 1) * D + t] = h1_1;
    h1T[t] = make_float2(h1_0, h1_1);
    __syncthreads();

    // ---- layer 2 ----
    bias = b2[t];
    a0 = bias; a1 = 0.f; c0 = bias; c1 = 0.f;
    K1_LAYER(W2, h1T, a0, a1, c0, c1)
    float h2_0 = tanhf(a0 + a1), h2_1 = tanhf(c0 + c1);
    d_H2[(s0 + 0) * D + t] = h2_0;
    d_H2[(s0 + 1) * D + t] = h2_1;
    float t20 = 1.f - h2_0 * h2_0, t21 = 1.f - h2_1 * h2_1;

#pragma unroll
    for (int a = 0; a < O; a++) {
        float w3 = W3[t * O + a];
        d_G2[((s0 + 0) * O + a) * D + t] = w3 * t20;
        d_G2[((s0 + 1) * O + a) * D + t] = w3 * t21;
    }
#undef K1_LAYER
}

// ======== kC: G1 backward (blocks 0..255) + pairwise dots (256..319) ==============
__global__ __launch_bounds__(256) void kC_bwd_dots(
    const float* __restrict__ x1, const float* __restrict__ x2)
{
    __shared__ float sm[5 * D];
    const int b = blockIdx.x, t = threadIdx.x;

    if (b < 256) {
        const int s = b >> 1, half = b & 1;
#pragma unroll
        for (int j = 0; j < 5; j++)
            sm[j * D + t] = d_G2[(s * O + half * 5 + j) * D + t];
        float h1 = d_H1[s * D + t];
        float t1 = 1.0f - h1 * h1;
        __syncthreads();

        float a0 = 0.f, a1 = 0.f, a2 = 0.f, a3 = 0.f, a4 = 0.f;
#pragma unroll 4
        for (int k4 = 0; k4 < 64; k4++) {
            float4 w  = *(const float4*)&d_W2P[(k4 * D + t) * 4];
            float4 g0 = *(const float4*)&sm[0 * D + k4 * 4];
            float4 g1 = *(const float4*)&sm[1 * D + k4 * 4];
            float4 g2 = *(const float4*)&sm[2 * D + k4 * 4];
            float4 g3 = *(const float4*)&sm[3 * D + k4 * 4];
            float4 g4 = *(const float4*)&sm[4 * D + k4 * 4];
            a0 += w.x * g0.x + w.y * g0.y + w.z * g0.z + w.w * g0.w;
            a1 += w.x * g1.x + w.y * g1.y + w.z * g1.z + w.w * g1.w;
            a2 += w.x * g2.x + w.y * g2.y + w.z * g2.z + w.w * g2.w;
            a3 += w.x * g3.x + w.y * g3.y + w.z * g3.z + w.w * g3.w;
            a4 += w.x * g4.x + w.y * g4.y + w.z * g4.z + w.w * g4.w;
        }
        const int base = (s * O + half * 5) * D + t;
        d_G1[base + 0 * D] = t1 * a0;
        d_G1[base + 1 * D] = t1 * a1;
        d_G1[base + 2 * D] = t1 * a2;
        d_G1[base + 3 * D] = t1 * a3;
        d_G1[base + 4 * D] = t1 * a4;
        return;
    }

    const int n = b - 256;
    float* xa  = sm;
    float* h1a = sm + D;
    float* h2a = sm + 2 * D;
    xa[t]  = x1[n * D + t];
    h1a[t] = d_H1[n * D + t];
    h2a[t] = d_H2[n * D + t];
    __syncthreads();

    const int warp = t >> 5, lane = t & 31;
#pragma unroll
    for (int mi = 0; mi < 8; mi++) {
        int m = warp * 8 + mi;
        const float* x2r = x2 + m * D;
        const float* h1r = d_H1 + (NS + m) * D;
        const float* h2r = d_H2 + (NS + m) * D;
        float s0 = 0.f, s1 = 0.f, s2 = 0.f;
#pragma unroll
        for (int k = lane; k < D; k += 32) {
            s0 += xa[k]  * x2r[k];
            s1 += h1a[k] * h1r[k];
            s2 += h2a[k] * h2r[k];
        }
#pragma unroll
        for (int off = 16; off > 0; off >>= 1) {
            s0 += __shfl_down_sync(0xffffffffu, s0, off);
            s1 += __shfl_down_sync(0xffffffffu, s1, off);
            s2 += __shfl_down_sync(0xffffffffu, s2, off);
        }
        if (lane == 0) {
            d_C[0][n * NS + m] = s0 + 1.0f;
            d_C[1][n * NS + m] = s1 + 1.0f;
            d_C[2][n * NS + m] = s2 + 1.0f;
        }
    }
}

// ======== kP: tensor-core pair-GEMMs (3xTF32, both layers) + fused NTK combine ====
// R13 version (software-pipelined LDG, measured good): 64x64 tile, 512 thr,
// 16 flattened stages; stage st+1's LDGs overlap stage st's MMAs.
__global__ __launch_bounds__(512) void kP_pair(float* __restrict__ out)
{
    __shared__ float sAhi[64][36];
    __shared__ float sAlo[64][36];
    __shared__ float sBhi[64][36];
    __shared__ float sBlo[64][36];

    const int tid  = threadIdx.x;
    const int lane = tid & 31;
    const int w    = tid >> 5;      // 0..15
    const int g    = lane >> 2;
    const int t4   = lane & 3;
    const int rt   = w & 3;
    const int cq   = w >> 2;        // 0..3
    const int r0 = blockIdx.y * 64, c0 = blockIdx.x * 64;

    float acc_h[2][2][4];
    float acc_c[2][2][4];
#pragma unroll
    for (int l = 0; l < 2; l++)
#pragma unroll
        for (int nt = 0; nt < 2; nt++)
#pragma unroll
            for (int q = 0; q < 4; q++) { acc_h[l][nt][q] = 0.f; acc_c[l][nt][q] = 0.f; }

    const int srow = tid >> 3;           // 0..63
    const int sq   = (tid & 7) * 4;      // 0..28

#define KP_LDG(st) {                                                           \
    const float* G = ((st) < 8) ? d_G1 : d_G2;                                 \
    const int kc = ((st) & 7) * 32;                                            \
    va = *(const float4*)&G[(r0 + srow) * D + kc + sq];                        \
    vb = *(const float4*)&G[(R + c0 + srow) * D + kc + sq];                    \
}

#define KP_MMA(LI) {                                                           \
    _Pragma("unroll")                                                          \
    for (int kk = 0; kk < 4; kk++) {                                           \
        const int kb = kk * 8 + t4;                                            \
        const int ar = rt * 16 + g;                                            \
        uint32_t ah0 = __float_as_uint(sAhi[ar][kb]);                          \
        uint32_t ah1 = __float_as_uint(sAhi[ar + 8][kb]);                      \
        uint32_t ah2 = __float_as_uint(sAhi[ar][kb + 4]);                      \
        uint32_t ah3 = __float_as_uint(sAhi[ar + 8][kb + 4]);                  \
        uint32_t al0 = __float_as_uint(sAlo[ar][kb]);                          \
        uint32_t al1 = __float_as_uint(sAlo[ar + 8][kb]);                      \
        uint32_t al2 = __float_as_uint(sAlo[ar][kb + 4]);                      \
        uint32_t al3 = __float_as_uint(sAlo[ar + 8][kb + 4]);                  \
        _Pragma("unroll")                                                      \
        for (int nt = 0; nt < 2; nt++) {                                       \
            const int nb = cq * 16 + nt * 8 + g;                               \
            uint32_t bh0 = __float_as_uint(sBhi[nb][kb]);                      \
            uint32_t bh1 = __float_as_uint(sBhi[nb][kb + 4]);                  \
            uint32_t bl0 = __float_as_uint(sBlo[nb][kb]);                      \
            uint32_t bl1 = __float_as_uint(sBlo[nb][kb + 4]);                  \
            float* chh = acc_h[LI][nt];                                        \
            float* ccr = acc_c[LI][nt];                                        \
            mma_tf32(chh[0], chh[1], chh[2], chh[3], ah0, ah1, ah2, ah3, bh0, bh1); \
            mma_tf32(ccr[0], ccr[1], ccr[2], ccr[3], ah0, ah1, ah2, ah3, bl0, bl1); \
            mma_tf32(ccr[0], ccr[1], ccr[2], ccr[3], al0, al1, al2, al3, bh0, bh1); \
        }                                                                      \
    } }

    float4 va, vb;
    KP_LDG(0)

#pragma unroll 1
    for (int st = 0; st < 16; st++) {
        {
            float av[4] = {va.x, va.y, va.z, va.w};
            float bv[4] = {vb.x, vb.y, vb.z, vb.w};
            float ah[4], al[4], bh[4], bl[4];
#pragma unroll
            for (int j = 0; j < 4; j++) {
                uint32_t h = f2tf32(av[j]);
                ah[j] = __uint_as_float(h);
                al[j] = __uint_as_float(f2tf32(av[j] - ah[j]));
                h = f2tf32(bv[j]);
                bh[j] = __uint_as_float(h);
                bl[j] = __uint_as_float(f2tf32(bv[j] - bh[j]));
            }
            *(float4*)&sAhi[srow][sq] = make_float4(ah[0], ah[1], ah[2], ah[3]);
            *(float4*)&sAlo[srow][sq] = make_float4(al[0], al[1], al[2], al[3]);
            *(float4*)&sBhi[srow][sq] = make_float4(bh[0], bh[1], bh[2], bh[3]);
            *(float4*)&sBlo[srow][sq] = make_float4(bl[0], bl[1], bl[2], bl[3]);
        }
        __syncthreads();

        if (st < 15) KP_LDG(st + 1)

        if (st < 8) { KP_MMA(0) } else { KP_MMA(1) }
        __syncthreads();
    }
#undef KP_LDG
#undef KP_MMA

    // ---- epilogue: out[n,m,a,b] = C0*P0 + C1*P1 + (a==b)*C2 ----
    const float* C0 = d_C[0];
    const float* C1 = d_C[1];
    const float* C2 = d_C[2];
#pragma unroll
    for (int nt = 0; nt < 2; nt++) {
        int col = c0 + cq * 16 + nt * 8 + 2 * t4;
        int m0 = col / 10,       bb0 = col - m0 * 10;
        int m1 = (col + 1) / 10, bb1 = (col + 1) - m1 * 10;
#pragma unroll
        for (int half = 0; half < 2; half++) {
            int row = r0 + rt * 16 + g + half * 8;
            int n = row / 10, a = row - n * 10;
            int ci0 = n * NS + m0, ci1 = n * NS + m1;
            float p00 = acc_h[0][nt][half * 2 + 0] + acc_c[0][nt][half * 2 + 0];
            float p10 = acc_h[1][nt][half * 2 + 0] + acc_c[1][nt][half * 2 + 0];
            float p01 = acc_h[0][nt][half * 2 + 1] + acc_c[0][nt][half * 2 + 1];
            float p11 = acc_h[1][nt][half * 2 + 1] + acc_c[1][nt][half * 2 + 1];
            float v0 = C0[ci0] * p00 + C1[ci0] * p10;
            float v1 = C0[ci1] * p01 + C1[ci1] * p11;
            if (a == bb0) v0 += C2[ci0];
            if (a == bb1) v1 += C2[ci1];
            out[ci0 * 100 + a * 10 + bb0] = v0;
            out[ci1 * 100 + a * 10 + bb1] = v1;
        }
    }
}

// ---------------- launcher ----------------
extern "C" void kernel_launch(void* const* d_in, const int* in_sizes, int n_in,
                              void* d_out, int out_size) {
    const float* x1 = (const float*)d_in[0];
    const float* x2 = (const float*)d_in[1];
    const float* W1 = (const float*)d_in[2];
    const float* b1 = (const float*)d_in[3];
    const float* W2 = (const float*)d_in[4];
    const float* b2 = (const float*)d_in[5];
    const float* W3 = (const float*)d_in[6];
    float* out = (float*)d_out;

    k1_fwd<<<128, 256>>>(x1, x2, W1, b1, W2, b2, W3);
    kC_bwd_dots<<<320, 256>>>(x1, x2);
    kP_pair<<<dim3(10, 10), 512>>>(out);
}

// round 15
// speedup vs baseline: 1.0944x; 1.0410x over previous
#include <cuda_runtime.h>
#include <math.h>
#include <stdint.h>

#define D 256
#define O 10
#define NS 64
#define R 640   // NS*O

// ---------------- scratch ----------------
__device__ float d_W2P[D * D];     // float4 at (k4*D + t) holds W2[t][4k4..4k4+3]
__device__ float d_H1[2 * NS * D];
__device__ float d_H2[2 * NS * D];
__device__ float d_G1[2 * R * D];
__device__ float d_G2[2 * R * D];
__device__ float d_C[3][NS * NS];

// ---------------- tf32 helpers ----------------
__device__ __forceinline__ uint32_t f2tf32(float f) {
    uint32_t r;
    asm("cvt.rna.tf32.f32 %0, %1;" : "=r"(r) : "f"(f));
    return r;
}
__device__ __forceinline__ void mma_tf32(
    float& c0, float& c1, float& c2, float& c3,
    uint32_t a0, uint32_t a1, uint32_t a2, uint32_t a3,
    uint32_t b0, uint32_t b1)
{
    asm volatile(
        "mma.sync.aligned.m16n8k8.row.col.f32.tf32.tf32.f32 "
        "{%0,%1,%2,%3}, {%4,%5,%6,%7}, {%8,%9}, {%0,%1,%2,%3};"
        : "+f"(c0), "+f"(c1), "+f"(c2), "+f"(c3)
        : "r"(a0), "r"(a1), "r"(a2), "r"(a3), "r"(b0), "r"(b1));
}

// ================= K1: W2 pack (blocks 0..63) + fused forward, 2 samples/CTA =====
// Prefetch-distance-2 register pipeline: 3 rotating 16-wide W buffers, so the
// issue->consume window (~2 batches) covers the ~600cyc load latency.
__global__ __launch_bounds__(256, 1) void k1_fwd(
    const float* __restrict__ x1, const float* __restrict__ x2,
    const float* __restrict__ W1, const float* __restrict__ b1,
    const float* __restrict__ W2, const float* __restrict__ b2,
    const float* __restrict__ W3)
{
    __shared__ __align__(8) float2 xT[D];
    __shared__ __align__(8) float2 h1T[D];

    const int b = blockIdx.x, t = threadIdx.x;

    if (b < 64) {
        int gid = b * 256 + t;
        int k4 = gid & 63, tw = gid >> 6;
        float4 v = *(const float4*)&W2[tw * D + k4 * 4];
        *(float4*)&d_W2P[(k4 * D + tw) * 4] = v;
        return;
    }

    const int s0 = (b - 64) * 2;
    const float* xr0 = (s0 < NS) ? (x1 + s0 * D) : (x2 + (s0 - NS) * D);
    const float* xr1 = (s0 + 1 < NS) ? (x1 + (s0 + 1) * D) : (x2 + (s0 + 1 - NS) * D);
    xT[t] = make_float2(xr0[t], xr1[t]);
    __syncthreads();

    float wA[16], wB[16], wC[16];

    // load 16-wide half-batch hb into BUF (hb compile-time; guarded off past end)
#define HB_LOAD(BUF, Wp, hb) {                                                 \
    if ((hb) < 16) {                                                           \
        _Pragma("unroll")                                                      \
        for (int j = 0; j < 16; j++) BUF[j] = (Wp)[((hb) * 16 + j) * D + t];   \
    } }
#define HB_COMP(BUF, SRC, hb, A0, A1, C0, C1) {                                \
    _Pragma("unroll")                                                          \
    for (int j = 0; j < 16; j += 2) {                                          \
        float2 xa = SRC[(hb) * 16 + j], xb = SRC[(hb) * 16 + j + 1];           \
        A0 += xa.x * BUF[j];     C0 += xa.y * BUF[j];                          \
        A1 += xb.x * BUF[j + 1]; C1 += xb.y * BUF[j + 1];                      \
    } }
#define HB_STEP(CUR, NXT, Wp, SRC, hb, A0, A1, C0, C1)                         \
    HB_LOAD(NXT, Wp, (hb) + 2)                                                 \
    HB_COMP(CUR, SRC, hb, A0, A1, C0, C1)

#define K1_LAYER(Wp, SRC, A0, A1, C0, C1)                                      \
    HB_LOAD(wA, Wp, 0)                                                         \
    HB_LOAD(wB, Wp, 1)                                                         \
    _Pragma("unroll")                                                          \
    for (int blk = 0; blk < 5; blk++) {                                        \
        HB_STEP(wA, wC, Wp, SRC, blk * 3 + 0, A0, A1, C0, C1)                  \
        HB_STEP(wB, wA, Wp, SRC, blk * 3 + 1, A0, A1, C0, C1)                  \
        HB_STEP(wC, wB, Wp, SRC, blk * 3 + 2, A0, A1, C0, C1)                  \
    }                                                                          \
    HB_COMP(wA, SRC, 15, A0, A1, C0, C1)

    // ---- layer 1 ----
    float bias = b1[t];
    float a0 = bias, a1 = 0.f, c0 = bias, c1 = 0.f;
    K1_LAYER(W1, xT, a0, a1, c0, c1)
    float h1_0 = tanhf(a0 + a1), h1_1 = tanhf(c0 + c1);
    d_H1[(s0 + 0) * D + t] = h1_0;
    d_H1[(s0 + 1) * D + t] = h1_1;
    h1T[t] = make_float2(h1_0, h1_1);
    __syncthreads();

    // ---- layer 2 ----
    bias = b2[t];
    a0 = bias; a1 = 0.f; c0 = bias; c1 = 0.f;
    K1_LAYER(W2, h1T, a0, a1, c0, c1)
    float h2_0 = tanhf(a0 + a1), h2_1 = tanhf(c0 + c1);
    d_H2[(s0 + 0) * D + t] = h2_0;
    d_H2[(s0 + 1) * D + t] = h2_1;
    float t20 = 1.f - h2_0 * h2_0, t21 = 1.f - h2_1 * h2_1;

#pragma unroll
    for (int a = 0; a < O; a++) {
        float w3 = W3[t * O + a];
        d_G2[((s0 + 0) * O + a) * D + t] = w3 * t20;
        d_G2[((s0 + 1) * O + a) * D + t] = w3 * t21;
    }
#undef K1_LAYER
#undef HB_STEP
#undef HB_COMP
#undef HB_LOAD
}

// ======== kC: G1 backward (blocks 0..255) + pairwise dots (256..319) ==============
__global__ __launch_bounds__(256) void kC_bwd_dots(
    const float* __restrict__ x1, const float* __restrict__ x2)
{
    __shared__ float sm[5 * D];
    const int b = blockIdx.x, t = threadIdx.x;

    if (b < 256) {
        const int s = b >> 1, half = b & 1;
#pragma unroll
        for (int j = 0; j < 5; j++)
            sm[j * D + t] = d_G2[(s * O + half * 5 + j) * D + t];
        float h1 = d_H1[s * D + t];
        float t1 = 1.0f - h1 * h1;
        __syncthreads();

        float a0 = 0.f, a1 = 0.f, a2 = 0.f, a3 = 0.f, a4 = 0.f;
#pragma unroll 4
        for (int k4 = 0; k4 < 64; k4++) {
            float4 w  = *(const float4*)&d_W2P[(k4 * D + t) * 4];
            float4 g0 = *(const float4*)&sm[0 * D + k4 * 4];
            float4 g1 = *(const float4*)&sm[1 * D + k4 * 4];
            float4 g2 = *(const float4*)&sm[2 * D + k4 * 4];
            float4 g3 = *(const float4*)&sm[3 * D + k4 * 4];
            float4 g4 = *(const float4*)&sm[4 * D + k4 * 4];
            a0 += w.x * g0.x + w.y * g0.y + w.z * g0.z + w.w * g0.w;
            a1 += w.x * g1.x + w.y * g1.y + w.z * g1.z + w.w * g1.w;
            a2 += w.x * g2.x + w.y * g2.y + w.z * g2.z + w.w * g2.w;
            a3 += w.x * g3.x + w.y * g3.y + w.z * g3.z + w.w * g3.w;
            a4 += w.x * g4.x + w.y * g4.y + w.z * g4.z + w.w * g4.w;
        }
        const int base = (s * O + half * 5) * D + t;
        d_G1[base + 0 * D] = t1 * a0;
        d_G1[base + 1 * D] = t1 * a1;
        d_G1[base + 2 * D] = t1 * a2;
        d_G1[base + 3 * D] = t1 * a3;
        d_G1[base + 4 * D] = t1 * a4;
        return;
    }

    const int n = b - 256;
    float* xa  = sm;
    float* h1a = sm + D;
    float* h2a = sm + 2 * D;
    xa[t]  = x1[n * D + t];
    h1a[t] = d_H1[n * D + t];
    h2a[t] = d_H2[n * D + t];
    __syncthreads();

    const int warp = t >> 5, lane = t & 31;
#pragma unroll
    for (int mi = 0; mi < 8; mi++) {
        int m = warp * 8 + mi;
        const float* x2r = x2 + m * D;
        const float* h1r = d_H1 + (NS + m) * D;
        const float* h2r = d_H2 + (NS + m) * D;
        float s0 = 0.f, s1 = 0.f, s2 = 0.f;
#pragma unroll
        for (int k = lane; k < D; k += 32) {
            s0 += xa[k]  * x2r[k];
            s1 += h1a[k] * h1r[k];
            s2 += h2a[k] * h2r[k];
        }
#pragma unroll
        for (int off = 16; off > 0; off >>= 1) {
            s0 += __shfl_down_sync(0xffffffffu, s0, off);
            s1 += __shfl_down_sync(0xffffffffu, s1, off);
            s2 += __shfl_down_sync(0xffffffffu, s2, off);
        }
        if (lane == 0) {
            d_C[0][n * NS + m] = s0 + 1.0f;
            d_C[1][n * NS + m] = s1 + 1.0f;
            d_C[2][n * NS + m] = s2 + 1.0f;
        }
    }
}

// ======== kP: tensor-core pair-GEMMs (3xTF32, both layers) + fused NTK combine ====
// R13/R14 version (software-pipelined LDG): 64x64 tile, 512 thr, 16 stages.
__global__ __launch_bounds__(512) void kP_pair(float* __restrict__ out)
{
    __shared__ float sAhi[64][36];
    __shared__ float sAlo[64][36];
    __shared__ float sBhi[64][36];
    __shared__ float sBlo[64][36];

    const int tid  = threadIdx.x;
    const int lane = tid & 31;
    const int w    = tid >> 5;
    const int g    = lane >> 2;
    const int t4   = lane & 3;
    const int rt   = w & 3;
    const int cq   = w >> 2;
    const int r0 = blockIdx.y * 64, c0 = blockIdx.x * 64;

    float acc_h[2][2][4];
    float acc_c[2][2][4];
#pragma unroll
    for (int l = 0; l < 2; l++)
#pragma unroll
        for (int nt = 0; nt < 2; nt++)
#pragma unroll
            for (int q = 0; q < 4; q++) { acc_h[l][nt][q] = 0.f; acc_c[l][nt][q] = 0.f; }

    const int srow = tid >> 3;
    const int sq   = (tid & 7) * 4;

#define KP_LDG(st) {                                                           \
    const float* G = ((st) < 8) ? d_G1 : d_G2;                                 \
    const int kc = ((st) & 7) * 32;                                            \
    va = *(const float4*)&G[(r0 + srow) * D + kc + sq];                        \
    vb = *(const float4*)&G[(R + c0 + srow) * D + kc + sq];                    \
}

#define KP_MMA(LI) {                                                           \
    _Pragma("unroll")                                                          \
    for (int kk = 0; kk < 4; kk++) {                                           \
        const int kb = kk * 8 + t4;                                            \
        const int ar = rt * 16 + g;                                            \
        uint32_t ah0 = __float_as_uint(sAhi[ar][kb]);                          \
        uint32_t ah1 = __float_as_uint(sAhi[ar + 8][kb]);                      \
        uint32_t ah2 = __float_as_uint(sAhi[ar][kb + 4]);                      \
        uint32_t ah3 = __float_as_uint(sAhi[ar + 8][kb + 4]);                  \
        uint32_t al0 = __float_as_uint(sAlo[ar][kb]);                          \
        uint32_t al1 = __float_as_uint(sAlo[ar + 8][kb]);                      \
        uint32_t al2 = __float_as_uint(sAlo[ar][kb + 4]);                      \
        uint32_t al3 = __float_as_uint(sAlo[ar + 8][kb + 4]);                  \
        _Pragma("unroll")                                                      \
        for (int nt = 0; nt < 2; nt++) {                                       \
            const int nb = cq * 16 + nt * 8 + g;                               \
            uint32_t bh0 = __float_as_uint(sBhi[nb][kb]);                      \
            uint32_t bh1 = __float_as_uint(sBhi[nb][kb + 4]);                  \
            uint32_t bl0 = __float_as_uint(sBlo[nb][kb]);                      \
            uint32_t bl1 = __float_as_uint(sBlo[nb][kb + 4]);                  \
            float* chh = acc_h[LI][nt];                                        \
            float* ccr = acc_c[LI][nt];                                        \
            mma_tf32(chh[0], chh[1], chh[2], chh[3], ah0, ah1, ah2, ah3, bh0, bh1); \
            mma_tf32(ccr[0], ccr[1], ccr[2], ccr[3], ah0, ah1, ah2, ah3, bl0, bl1); \
            mma_tf32(ccr[0], ccr[1], ccr[2], ccr[3], al0, al1, al2, al3, bh0, bh1); \
        }                                                                      \
    } }

    float4 va, vb;
    KP_LDG(0)

#pragma unroll 1
    for (int st = 0; st < 16; st++) {
        {
            float av[4] = {va.x, va.y, va.z, va.w};
            float bv[4] = {vb.x, vb.y, vb.z, vb.w};
            float ah[4], al[4], bh[4], bl[4];
#pragma unroll
            for (int j = 0; j < 4; j++) {
                uint32_t h = f2tf32(av[j]);
                ah[j] = __uint_as_float(h);
                al[j] = __uint_as_float(f2tf32(av[j] - ah[j]));
                h = f2tf32(bv[j]);
                bh[j] = __uint_as_float(h);
                bl[j] = __uint_as_float(f2tf32(bv[j] - bh[j]));
            }
            *(float4*)&sAhi[srow][sq] = make_float4(ah[0], ah[1], ah[2], ah[3]);
            *(float4*)&sAlo[srow][sq] = make_float4(al[0], al[1], al[2], al[3]);
            *(float4*)&sBhi[srow][sq] = make_float4(bh[0], bh[1], bh[2], bh[3]);
            *(float4*)&sBlo[srow][sq] = make_float4(bl[0], bl[1], bl[2], bl[3]);
        }
        __syncthreads();

        if (st < 15) KP_LDG(st + 1)

        if (st < 8) { KP_MMA(0) } else { KP_MMA(1) }
        __syncthreads();
    }
#undef KP_LDG
#undef KP_MMA

    // ---- epilogue: out[n,m,a,b] = C0*P0 + C1*P1 + (a==b)*C2 ----
    const float* C0 = d_C[0];
    const float* C1 = d_C[1];
    const float* C2 = d_C[2];
#pragma unroll
    for (int nt = 0; nt < 2; nt++) {
        int col = c0 + cq * 16 + nt * 8 + 2 * t4;
        int m0 = col / 10,       bb0 = col - m0 * 10;
        int m1 = (col + 1) / 10, bb1 = (col + 1) - m1 * 10;
#pragma unroll
        for (int half = 0; half < 2; half++) {
            int row = r0 + rt * 16 + g + half * 8;
            int n = row / 10, a = row - n * 10;
            int ci0 = n * NS + m0, ci1 = n * NS + m1;
            float p00 = acc_h[0][nt][half * 2 + 0] + acc_c[0][nt][half * 2 + 0];
            float p10 = acc_h[1][nt][half * 2 + 0] + acc_c[1][nt][half * 2 + 0];
            float p01 = acc_h[0][nt][half * 2 + 1] + acc_c[0][nt][half * 2 + 1];
            float p11 = acc_h[1][nt][half * 2 + 1] + acc_c[1][nt][half * 2 + 1];
            float v0 = C0[ci0] * p00 + C1[ci0] * p10;
            float v1 = C0[ci1] * p01 + C1[ci1] * p11;
            if (a == bb0) v0 += C2[ci0];
            if (a == bb1) v1 += C2[ci1];
            out[ci0 * 100 + a * 10 + bb0] = v0;
            out[ci1 * 100 + a * 10 + bb1] = v1;
        }
    }
}

// ---------------- launcher ----------------
extern "C" void kernel_launch(void* const* d_in, const int* in_sizes, int n_in,
                              void* d_out, int out_size) {
    const float* x1 = (const float*)d_in[0];
    const float* x2 = (const float*)d_in[1];
    const float* W1 = (const float*)d_in[2];
    const float* b1 = (const float*)d_in[3];
    const float* W2 = (const float*)d_in[4];
    const float* b2 = (const float*)d_in[5];
    const float* W3 = (const float*)d_in[6];
    float* out = (float*)d_out;

    k1_fwd<<<128, 256>>>(x1, x2, W1, b1, W2, b2, W3);
    kC_bwd_dots<<<320, 256>>>(x1, x2);
    kP_pair<<<dim3(10, 10), 512>>>(out);
}

// round 16
// speedup vs baseline: 1.1465x; 1.0475x over previous
#include <cuda_runtime.h>
#include <math.h>
#include <stdint.h>

#define D 256
#define O 10
#define NS 64
#define R 640   // NS*O

// ---------------- scratch ----------------
__device__ float d_W2P[D * D];     // float4 at (k4*D + t) holds W2[t][4k4..4k4+3]
__device__ float d_H1[2 * NS * D];
__device__ float d_H2[2 * NS * D];
__device__ float d_G1[2 * R * D];
__device__ float d_G2[2 * R * D];
__device__ float d_C[3][NS * NS];

// ---------------- tf32 helpers ----------------
__device__ __forceinline__ uint32_t f2tf32(float f) {
    uint32_t r;
    asm("cvt.rna.tf32.f32 %0, %1;" : "=r"(r) : "f"(f));
    return r;
}
__device__ __forceinline__ void mma_tf32(
    float& c0, float& c1, float& c2, float& c3,
    uint32_t a0, uint32_t a1, uint32_t a2, uint32_t a3,
    uint32_t b0, uint32_t b1)
{
    asm volatile(
        "mma.sync.aligned.m16n8k8.row.col.f32.tf32.tf32.f32 "
        "{%0,%1,%2,%3}, {%4,%5,%6,%7}, {%8,%9}, {%0,%1,%2,%3};"
        : "+f"(c0), "+f"(c1), "+f"(c2), "+f"(c3)
        : "r"(a0), "r"(a1), "r"(a2), "r"(a3), "r"(b0), "r"(b1));
}

// ================= K1: W2 pack (blocks 0..63) + fused forward, 2 samples/CTA =====
// Prefetch-distance-2 register pipeline (R15, measured 10.9us).
__global__ __launch_bounds__(256, 1) void k1_fwd(
    const float* __restrict__ x1, const float* __restrict__ x2,
    const float* __restrict__ W1, const float* __restrict__ b1,
    const float* __restrict__ W2, const float* __restrict__ b2,
    const float* __restrict__ W3)
{
    __shared__ __align__(8) float2 xT[D];
    __shared__ __align__(8) float2 h1T[D];

    const int b = blockIdx.x, t = threadIdx.x;

    if (b < 64) {
        int gid = b * 256 + t;
        int k4 = gid & 63, tw = gid >> 6;
        float4 v = *(const float4*)&W2[tw * D + k4 * 4];
        *(float4*)&d_W2P[(k4 * D + tw) * 4] = v;
        return;
    }

    const int s0 = (b - 64) * 2;
    const float* xr0 = (s0 < NS) ? (x1 + s0 * D) : (x2 + (s0 - NS) * D);
    const float* xr1 = (s0 + 1 < NS) ? (x1 + (s0 + 1) * D) : (x2 + (s0 + 1 - NS) * D);
    xT[t] = make_float2(xr0[t], xr1[t]);
    __syncthreads();

    float wA[16], wB[16], wC[16];

#define HB_LOAD(BUF, Wp, hb) {                                                 \
    if ((hb) < 16) {                                                           \
        _Pragma("unroll")                                                      \
        for (int j = 0; j < 16; j++) BUF[j] = (Wp)[((hb) * 16 + j) * D + t];   \
    } }
#define HB_COMP(BUF, SRC, hb, A0, A1, C0, C1) {                                \
    _Pragma("unroll")                                                          \
    for (int j = 0; j < 16; j += 2) {                                          \
        float2 xa = SRC[(hb) * 16 + j], xb = SRC[(hb) * 16 + j + 1];           \
        A0 += xa.x * BUF[j];     C0 += xa.y * BUF[j];                          \
        A1 += xb.x * BUF[j + 1]; C1 += xb.y * BUF[j + 1];                      \
    } }
#define HB_STEP(CUR, NXT, Wp, SRC, hb, A0, A1, C0, C1)                         \
    HB_LOAD(NXT, Wp, (hb) + 2)                                                 \
    HB_COMP(CUR, SRC, hb, A0, A1, C0, C1)

#define K1_LAYER(Wp, SRC, A0, A1, C0, C1)                                      \
    HB_LOAD(wA, Wp, 0)                                                         \
    HB_LOAD(wB, Wp, 1)                                                         \
    _Pragma("unroll")                                                          \
    for (int blk = 0; blk < 5; blk++) {                                        \
        HB_STEP(wA, wC, Wp, SRC, blk * 3 + 0, A0, A1, C0, C1)                  \
        HB_STEP(wB, wA, Wp, SRC, blk * 3 + 1, A0, A1, C0, C1)                  \
        HB_STEP(wC, wB, Wp, SRC, blk * 3 + 2, A0, A1, C0, C1)                  \
    }                                                                          \
    HB_COMP(wA, SRC, 15, A0, A1, C0, C1)

    // ---- layer 1 ----
    float bias = b1[t];
    float a0 = bias, a1 = 0.f, c0 = bias, c1 = 0.f;
    K1_LAYER(W1, xT, a0, a1, c0, c1)
    float h1_0 = tanhf(a0 + a1), h1_1 = tanhf(c0 + c1);
    d_H1[(s0 + 0) * D + t] = h1_0;
    d_H1[(s0 + 1) * D + t] = h1_1;
    h1T[t] = make_float2(h1_0, h1_1);
    __syncthreads();

    // ---- layer 2 ----
    bias = b2[t];
    a0 = bias; a1 = 0.f; c0 = bias; c1 = 0.f;
    K1_LAYER(W2, h1T, a0, a1, c0, c1)
    float h2_0 = tanhf(a0 + a1), h2_1 = tanhf(c0 + c1);
    d_H2[(s0 + 0) * D + t] = h2_0;
    d_H2[(s0 + 1) * D + t] = h2_1;
    float t20 = 1.f - h2_0 * h2_0, t21 = 1.f - h2_1 * h2_1;

#pragma unroll
    for (int a = 0; a < O; a++) {
        float w3 = W3[t * O + a];
        d_G2[((s0 + 0) * O + a) * D + t] = w3 * t20;
        d_G2[((s0 + 1) * O + a) * D + t] = w3 * t21;
    }
#undef K1_LAYER
#undef HB_STEP
#undef HB_COMP
#undef HB_LOAD
}

// ======== kC: G1 backward (blocks 0..255) + pairwise dots (256..319) ==============
__global__ __launch_bounds__(256) void kC_bwd_dots(
    const float* __restrict__ x1, const float* __restrict__ x2)
{
    __shared__ float sm[5 * D];
    const int b = blockIdx.x, t = threadIdx.x;

    if (b < 256) {
        const int s = b >> 1, half = b & 1;
#pragma unroll
        for (int j = 0; j < 5; j++)
            sm[j * D + t] = d_G2[(s * O + half * 5 + j) * D + t];
        float h1 = d_H1[s * D + t];
        float t1 = 1.0f - h1 * h1;
        __syncthreads();

        float a0 = 0.f, a1 = 0.f, a2 = 0.f, a3 = 0.f, a4 = 0.f;
#pragma unroll 4
        for (int k4 = 0; k4 < 64; k4++) {
            float4 w  = *(const float4*)&d_W2P[(k4 * D + t) * 4];
            float4 g0 = *(const float4*)&sm[0 * D + k4 * 4];
            float4 g1 = *(const float4*)&sm[1 * D + k4 * 4];
            float4 g2 = *(const float4*)&sm[2 * D + k4 * 4];
            float4 g3 = *(const float4*)&sm[3 * D + k4 * 4];
            float4 g4 = *(const float4*)&sm[4 * D + k4 * 4];
            a0 += w.x * g0.x + w.y * g0.y + w.z * g0.z + w.w * g0.w;
            a1 += w.x * g1.x + w.y * g1.y + w.z * g1.z + w.w * g1.w;
            a2 += w.x * g2.x + w.y * g2.y + w.z * g2.z + w.w * g2.w;
            a3 += w.x * g3.x + w.y * g3.y + w.z * g3.z + w.w * g3.w;
            a4 += w.x * g4.x + w.y * g4.y + w.z * g4.z + w.w * g4.w;
        }
        const int base = (s * O + half * 5) * D + t;
        d_G1[base + 0 * D] = t1 * a0;
        d_G1[base + 1 * D] = t1 * a1;
        d_G1[base + 2 * D] = t1 * a2;
        d_G1[base + 3 * D] = t1 * a3;
        d_G1[base + 4 * D] = t1 * a4;
        return;
    }

    const int n = b - 256;
    float* xa  = sm;
    float* h1a = sm + D;
    float* h2a = sm + 2 * D;
    xa[t]  = x1[n * D + t];
    h1a[t] = d_H1[n * D + t];
    h2a[t] = d_H2[n * D + t];
    __syncthreads();

    const int warp = t >> 5, lane = t & 31;
#pragma unroll
    for (int mi = 0; mi < 8; mi++) {
        int m = warp * 8 + mi;
        const float* x2r = x2 + m * D;
        const float* h1r = d_H1 + (NS + m) * D;
        const float* h2r = d_H2 + (NS + m) * D;
        float s0 = 0.f, s1 = 0.f, s2 = 0.f;
#pragma unroll
        for (int k = lane; k < D; k += 32) {
            s0 += xa[k]  * x2r[k];
            s1 += h1a[k] * h1r[k];
            s2 += h2a[k] * h2r[k];
        }
#pragma unroll
        for (int off = 16; off > 0; off >>= 1) {
            s0 += __shfl_down_sync(0xffffffffu, s0, off);
            s1 += __shfl_down_sync(0xffffffffu, s1, off);
            s2 += __shfl_down_sync(0xffffffffu, s2, off);
        }
        if (lane == 0) {
            d_C[0][n * NS + m] = s0 + 1.0f;
            d_C[1][n * NS + m] = s1 + 1.0f;
            d_C[2][n * NS + m] = s2 + 1.0f;
        }
    }
}

// ======== kP: tensor-core pair-GEMMs (3xTF32) + combine, double-buffered smem =====
// 64x64 tile, 512 thr, 16 stages; per stage: split+STS -> buf[st&1], prefetch
// LDG(st+1), ONE sync, MMA(buf). Dynamic smem: 2 x (Ahi,Alo,Bhi,Blo)[64][36].
#define KP_BUF_FLOATS (4 * 64 * 36)            // one buffer: 9216 floats
#define KP_SMEM_BYTES (2 * KP_BUF_FLOATS * 4)  // 73728 bytes

__global__ __launch_bounds__(512) void kP_pair(float* __restrict__ out)
{
    extern __shared__ float dsm[];

    const int tid  = threadIdx.x;
    const int lane = tid & 31;
    const int w    = tid >> 5;
    const int g    = lane >> 2;
    const int t4   = lane & 3;
    const int rt   = w & 3;
    const int cq   = w >> 2;
    const int r0 = blockIdx.y * 64, c0 = blockIdx.x * 64;

    float acc_h[2][2][4];
    float acc_c[2][2][4];
#pragma unroll
    for (int l = 0; l < 2; l++)
#pragma unroll
        for (int nt = 0; nt < 2; nt++)
#pragma unroll
            for (int q = 0; q < 4; q++) { acc_h[l][nt][q] = 0.f; acc_c[l][nt][q] = 0.f; }

    const int srow = tid >> 3;
    const int sq   = (tid & 7) * 4;

    // buffer p base pointers: Ahi, Alo, Bhi, Blo each [64][36]
#define KP_AHI(p) (dsm + (p) * KP_BUF_FLOATS + 0 * 2304)
#define KP_ALO(p) (dsm + (p) * KP_BUF_FLOATS + 1 * 2304)
#define KP_BHI(p) (dsm + (p) * KP_BUF_FLOATS + 2 * 2304)
#define KP_BLO(p) (dsm + (p) * KP_BUF_FLOATS + 3 * 2304)

#define KP_LDG(st) {                                                           \
    const float* G = ((st) < 8) ? d_G1 : d_G2;                                 \
    const int kc = ((st) & 7) * 32;                                            \
    va = *(const float4*)&G[(r0 + srow) * D + kc + sq];                        \
    vb = *(const float4*)&G[(R + c0 + srow) * D + kc + sq];                    \
}

#define KP_MMA(p, LI) {                                                        \
    const float* pAhi = KP_AHI(p); const float* pAlo = KP_ALO(p);              \
    const float* pBhi = KP_BHI(p); const float* pBlo = KP_BLO(p);              \
    _Pragma("unroll")                                                          \
    for (int kk = 0; kk < 4; kk++) {                                           \
        const int kb = kk * 8 + t4;                                            \
        const int ar = rt * 16 + g;                                            \
        uint32_t ah0 = __float_as_uint(pAhi[ar * 36 + kb]);                    \
        uint32_t ah1 = __float_as_uint(pAhi[(ar + 8) * 36 + kb]);              \
        uint32_t ah2 = __float_as_uint(pAhi[ar * 36 + kb + 4]);                \
        uint32_t ah3 = __float_as_uint(pAhi[(ar + 8) * 36 + kb + 4]);          \
        uint32_t al0 = __float_as_uint(pAlo[ar * 36 + kb]);                    \
        uint32_t al1 = __float_as_uint(pAlo[(ar + 8) * 36 + kb]);              \
        uint32_t al2 = __float_as_uint(pAlo[ar * 36 + kb + 4]);                \
        uint32_t al3 = __float_as_uint(pAlo[(ar + 8) * 36 + kb + 4]);          \
        _Pragma("unroll")                                                      \
        for (int nt = 0; nt < 2; nt++) {                                       \
            const int nb = cq * 16 + nt * 8 + g;                               \
            uint32_t bh0 = __float_as_uint(pBhi[nb * 36 + kb]);                \
            uint32_t bh1 = __float_as_uint(pBhi[nb * 36 + kb + 4]);            \
            uint32_t bl0 = __float_as_uint(pBlo[nb * 36 + kb]);                \
            uint32_t bl1 = __float_as_uint(pBlo[nb * 36 + kb + 4]);            \
            float* chh = acc_h[LI][nt];                                        \
            float* ccr = acc_c[LI][nt];                                        \
            mma_tf32(chh[0], chh[1], chh[2], chh[3], ah0, ah1, ah2, ah3, bh0, bh1); \
            mma_tf32(ccr[0], ccr[1], ccr[2], ccr[3], ah0, ah1, ah2, ah3, bl0, bl1); \
            mma_tf32(ccr[0], ccr[1], ccr[2], ccr[3], al0, al1, al2, al3, bh0, bh1); \
        }                                                                      \
    } }

    float4 va, vb;
    KP_LDG(0)

#pragma unroll 1
    for (int st = 0; st < 16; st++) {
        const int p = st & 1;
        {
            float* pAhi = KP_AHI(p); float* pAlo = KP_ALO(p);
            float* pBhi = KP_BHI(p); float* pBlo = KP_BLO(p);
            float av[4] = {va.x, va.y, va.z, va.w};
            float bv[4] = {vb.x, vb.y, vb.z, vb.w};
            float ah[4], al[4], bh[4], bl[4];
#pragma unroll
            for (int j = 0; j < 4; j++) {
                uint32_t h = f2tf32(av[j]);
                ah[j] = __uint_as_float(h);
                al[j] = __uint_as_float(f2tf32(av[j] - ah[j]));
                h = f2tf32(bv[j]);
                bh[j] = __uint_as_float(h);
                bl[j] = __uint_as_float(f2tf32(bv[j] - bh[j]));
            }
            *(float4*)&pAhi[srow * 36 + sq] = make_float4(ah[0], ah[1], ah[2], ah[3]);
            *(float4*)&pAlo[srow * 36 + sq] = make_float4(al[0], al[1], al[2], al[3]);
            *(float4*)&pBhi[srow * 36 + sq] = make_float4(bh[0], bh[1], bh[2], bh[3]);
            *(float4*)&pBlo[srow * 36 + sq] = make_float4(bl[0], bl[1], bl[2], bl[3]);
        }
        if (st < 15) KP_LDG(st + 1)
        __syncthreads();
        if (st < 8) { KP_MMA(p, 0) } else { KP_MMA(p, 1) }
    }
#undef KP_LDG
#undef KP_MMA
#undef KP_AHI
#undef KP_ALO
#undef KP_BHI
#undef KP_BLO

    // ---- epilogue: out[n,m,a,b] = C0*P0 + C1*P1 + (a==b)*C2 ----
    const float* C0 = d_C[0];
    const float* C1 = d_C[1];
    const float* C2 = d_C[2];
#pragma unroll
    for (int nt = 0; nt < 2; nt++) {
        int col = c0 + cq * 16 + nt * 8 + 2 * t4;
        int m0 = col / 10,       bb0 = col - m0 * 10;
        int m1 = (col + 1) / 10, bb1 = (col + 1) - m1 * 10;
#pragma unroll
        for (int half = 0; half < 2; half++) {
            int row = r0 + rt * 16 + g + half * 8;
            int n = row / 10, a = row - n * 10;
            int ci0 = n * NS + m0, ci1 = n * NS + m1;
            float p00 = acc_h[0][nt][half * 2 + 0] + acc_c[0][nt][half * 2 + 0];
            float p10 = acc_h[1][nt][half * 2 + 0] + acc_c[1][nt][half * 2 + 0];
            float p01 = acc_h[0][nt][half * 2 + 1] + acc_c[0][nt][half * 2 + 1];
            float p11 = acc_h[1][nt][half * 2 + 1] + acc_c[1][nt][half * 2 + 1];
            float v0 = C0[ci0] * p00 + C1[ci0] * p10;
            float v1 = C0[ci1] * p01 + C1[ci1] * p11;
            if (a == bb0) v0 += C2[ci0];
            if (a == bb1) v1 += C2[ci1];
            out[ci0 * 100 + a * 10 + bb0] = v0;
            out[ci1 * 100 + a * 10 + bb1] = v1;
        }
    }
}

// ---------------- launcher ----------------
extern "C" void kernel_launch(void* const* d_in, const int* in_sizes, int n_in,
                              void* d_out, int out_size) {
    const float* x1 = (const float*)d_in[0];
    const float* x2 = (const float*)d_in[1];
    const float* W1 = (const float*)d_in[2];
    const float* b1 = (const float*)d_in[3];
    const float* W2 = (const float*)d_in[4];
    const float* b2 = (const float*)d_in[5];
    const float* W3 = (const float*)d_in[6];
    float* out = (float*)d_out;

    cudaFuncSetAttribute(kP_pair, cudaFuncAttributeMaxDynamicSharedMemorySize,
                         KP_SMEM_BYTES);

    k1_fwd<<<128, 256>>>(x1, x2, W1, b1, W2, b2, W3);
    kC_bwd_dots<<<320, 256>>>(x1, x2);
    kP_pair<<<dim3(10, 10), 512, KP_SMEM_BYTES>>>(out);
}

// round 17
// speedup vs baseline: 1.1544x; 1.0069x over previous
#include <cuda_runtime.h>
#include <math.h>
#include <stdint.h>

#define D 256
#define O 10
#define NS 64
#define R 640   // NS*O

// ---------------- scratch ----------------
__device__ float d_W2P[D * D];     // float4 at (k4*D + t) holds W2[t][4k4..4k4+3]
__device__ float d_H1[2 * NS * D];
__device__ float d_H2[2 * NS * D];
__device__ float d_G1[2 * R * D];
__device__ float d_G2[2 * R * D];
__device__ float d_C[3][NS * NS];

// ---------------- tf32 helpers ----------------
__device__ __forceinline__ uint32_t f2tf32(float f) {
    uint32_t r;
    asm("cvt.rna.tf32.f32 %0, %1;" : "=r"(r) : "f"(f));
    return r;
}
__device__ __forceinline__ void mma_tf32(
    float& c0, float& c1, float& c2, float& c3,
    uint32_t a0, uint32_t a1, uint32_t a2, uint32_t a3,
    uint32_t b0, uint32_t b1)
{
    asm volatile(
        "mma.sync.aligned.m16n8k8.row.col.f32.tf32.tf32.f32 "
        "{%0,%1,%2,%3}, {%4,%5,%6,%7}, {%8,%9}, {%0,%1,%2,%3};"
        : "+f"(c0), "+f"(c1), "+f"(c2), "+f"(c3)
        : "r"(a0), "r"(a1), "r"(a2), "r"(a3), "r"(b0), "r"(b1));
}

// ================= K1: W2 pack (blocks 0..31) + split-K forward (32..95) =========
// 512 threads: t = tid&255 -> output unit, kh = tid>>8 -> k half [kh*128, kh*128+128).
// Each half: prefetch-distance-2 register pipeline over 8 x 16-wide half-batches.
// kh=1 publishes partials to smem; kh=0 reduces, bias+tanh, publishes h1/t2.
__global__ __launch_bounds__(512, 1) void k1_fwd(
    const float* __restrict__ x1, const float* __restrict__ x2,
    const float* __restrict__ W1, const float* __restrict__ b1,
    const float* __restrict__ W2, const float* __restrict__ b2,
    const float* __restrict__ W3)
{
    __shared__ __align__(8) float2 xT[D];
    __shared__ __align__(8) float2 h1T[D];
    __shared__ __align__(8) float2 red[256];   // kh=1 partials
    __shared__ __align__(8) float2 t2s[256];   // (1-h2^2) per sample pair

    const int b = blockIdx.x, tid = threadIdx.x;

    if (b < 32) {
        int gid = b * 512 + tid;
        int k4 = gid & 63, tw = gid >> 6;
        float4 v = *(const float4*)&W2[tw * D + k4 * 4];
        *(float4*)&d_W2P[(k4 * D + tw) * 4] = v;
        return;
    }

    const int t  = tid & 255;
    const int kh = tid >> 8;            // 0 or 1
    const int kb0 = kh * 8;             // first half-batch index for this half
    const int s0 = (b - 32) * 2;

    if (kh == 0) {
        const float* xr0 = (s0 < NS) ? (x1 + s0 * D) : (x2 + (s0 - NS) * D);
        const float* xr1 = (s0 + 1 < NS) ? (x1 + (s0 + 1) * D) : (x2 + (s0 + 1 - NS) * D);
        xT[t] = make_float2(xr0[t], xr1[t]);
    }
    __syncthreads();

    float wA[16], wB[16], wC[16];

    // hb is local (0..7); global half-batch = kb0 + hb
#define HB_LOAD(BUF, Wp, hb) {                                                 \
    if ((hb) < 8) {                                                            \
        _Pragma("unroll")                                                      \
        for (int j = 0; j < 16; j++)                                           \
            BUF[j] = (Wp)[((kb0 + (hb)) * 16 + j) * D + t];                    \
    } }
#define HB_COMP(BUF, SRC, hb, A0, A1, C0, C1) {                                \
    _Pragma("unroll")                                                          \
    for (int j = 0; j < 16; j += 2) {                                          \
        float2 xa = SRC[(kb0 + (hb)) * 16 + j];                                \
        float2 xb = SRC[(kb0 + (hb)) * 16 + j + 1];                            \
        A0 += xa.x * BUF[j];     C0 += xa.y * BUF[j];                          \
        A1 += xb.x * BUF[j + 1]; C1 += xb.y * BUF[j + 1];                      \
    } }
#define HB_STEP(CUR, NXT, Wp, SRC, hb, A0, A1, C0, C1)                         \
    HB_LOAD(NXT, Wp, (hb) + 2)                                                 \
    HB_COMP(CUR, SRC, hb, A0, A1, C0, C1)

    // 8 half-batches: prologue(0,1), 2 blocks of 3 rotations, epilogue(6,7)
#define K1_LAYER(Wp, SRC, A0, A1, C0, C1)                                      \
    HB_LOAD(wA, Wp, 0)                                                         \
    HB_LOAD(wB, Wp, 1)                                                         \
    HB_STEP(wA, wC, Wp, SRC, 0, A0, A1, C0, C1)                                \
    HB_STEP(wB, wA, Wp, SRC, 1, A0, A1, C0, C1)                                \
    HB_STEP(wC, wB, Wp, SRC, 2, A0, A1, C0, C1)                                \
    HB_STEP(wA, wC, Wp, SRC, 3, A0, A1, C0, C1)                                \
    HB_STEP(wB, wA, Wp, SRC, 4, A0, A1, C0, C1)                                \
    HB_STEP(wC, wB, Wp, SRC, 5, A0, A1, C0, C1)                                \
    HB_COMP(wA, SRC, 6, A0, A1, C0, C1)                                        \
    HB_COMP(wB, SRC, 7, A0, A1, C0, C1)

    // ---- layer 1 ----
    float a0 = 0.f, a1 = 0.f, c0 = 0.f, c1 = 0.f;
    K1_LAYER(W1, xT, a0, a1, c0, c1)
    if (kh == 1) {
        red[t] = make_float2(a0 + a1, c0 + c1);
    }
    __syncthreads();
    if (kh == 0) {
        float bias = b1[t];
        float2 r = red[t];
        float h1_0 = tanhf(a0 + a1 + r.x + bias);
        float h1_1 = tanhf(c0 + c1 + r.y + bias);
        d_H1[(s0 + 0) * D + t] = h1_0;
        d_H1[(s0 + 1) * D + t] = h1_1;
        h1T[t] = make_float2(h1_0, h1_1);
    }
    __syncthreads();

    // ---- layer 2 ----
    a0 = 0.f; a1 = 0.f; c0 = 0.f; c1 = 0.f;
    K1_LAYER(W2, h1T, a0, a1, c0, c1)
    if (kh == 1) {
        red[t] = make_float2(a0 + a1, c0 + c1);
    }
    __syncthreads();
    if (kh == 0) {
        float bias = b2[t];
        float2 r = red[t];
        float h2_0 = tanhf(a0 + a1 + r.x + bias);
        float h2_1 = tanhf(c0 + c1 + r.y + bias);
        d_H2[(s0 + 0) * D + t] = h2_0;
        d_H2[(s0 + 1) * D + t] = h2_1;
        t2s[t] = make_float2(1.f - h2_0 * h2_0, 1.f - h2_1 * h2_1);
    }
    __syncthreads();

    // ---- G2[s,a,t] = W3[t,a] * (1 - h2^2); split a-range across halves ----
    {
        float2 t2 = t2s[t];
#pragma unroll
        for (int a = 0; a < 5; a++) {
            int aa = kh * 5 + a;
            float w3 = W3[t * O + aa];
            d_G2[((s0 + 0) * O + aa) * D + t] = w3 * t2.x;
            d_G2[((s0 + 1) * O + aa) * D + t] = w3 * t2.y;
        }
    }
#undef K1_LAYER
#undef HB_STEP
#undef HB_COMP
#undef HB_LOAD
}

// ======== kC: G1 backward (blocks 0..255) + pairwise dots (256..319) ==============
__global__ __launch_bounds__(256) void kC_bwd_dots(
    const float* __restrict__ x1, const float* __restrict__ x2)
{
    __shared__ float sm[5 * D];
    const int b = blockIdx.x, t = threadIdx.x;

    if (b < 256) {
        const int s = b >> 1, half = b & 1;
#pragma unroll
        for (int j = 0; j < 5; j++)
            sm[j * D + t] = d_G2[(s * O + half * 5 + j) * D + t];
        float h1 = d_H1[s * D + t];
        float t1 = 1.0f - h1 * h1;
        __syncthreads();

        float a0 = 0.f, a1 = 0.f, a2 = 0.f, a3 = 0.f, a4 = 0.f;
#pragma unroll 4
        for (int k4 = 0; k4 < 64; k4++) {
            float4 w  = *(const float4*)&d_W2P[(k4 * D + t) * 4];
            float4 g0 = *(const float4*)&sm[0 * D + k4 * 4];
            float4 g1 = *(const float4*)&sm[1 * D + k4 * 4];
            float4 g2 = *(const float4*)&sm[2 * D + k4 * 4];
            float4 g3 = *(const float4*)&sm[3 * D + k4 * 4];
            float4 g4 = *(const float4*)&sm[4 * D + k4 * 4];
            a0 += w.x * g0.x + w.y * g0.y + w.z * g0.z + w.w * g0.w;
            a1 += w.x * g1.x + w.y * g1.y + w.z * g1.z + w.w * g1.w;
            a2 += w.x * g2.x + w.y * g2.y + w.z * g2.z + w.w * g2.w;
            a3 += w.x * g3.x + w.y * g3.y + w.z * g3.z + w.w * g3.w;
            a4 += w.x * g4.x + w.y * g4.y + w.z * g4.z + w.w * g4.w;
        }
        const int base = (s * O + half * 5) * D + t;
        d_G1[base + 0 * D] = t1 * a0;
        d_G1[base + 1 * D] = t1 * a1;
        d_G1[base + 2 * D] = t1 * a2;
        d_G1[base + 3 * D] = t1 * a3;
        d_G1[base + 4 * D] = t1 * a4;
        return;
    }

    const int n = b - 256;
    float* xa  = sm;
    float* h1a = sm + D;
    float* h2a = sm + 2 * D;
    xa[t]  = x1[n * D + t];
    h1a[t] = d_H1[n * D + t];
    h2a[t] = d_H2[n * D + t];
    __syncthreads();

    const int warp = t >> 5, lane = t & 31;
#pragma unroll
    for (int mi = 0; mi < 8; mi++) {
        int m = warp * 8 + mi;
        const float* x2r = x2 + m * D;
        const float* h1r = d_H1 + (NS + m) * D;
        const float* h2r = d_H2 + (NS + m) * D;
        float s0 = 0.f, s1 = 0.f, s2 = 0.f;
#pragma unroll
        for (int k = lane; k < D; k += 32) {
            s0 += xa[k]  * x2r[k];
            s1 += h1a[k] * h1r[k];
            s2 += h2a[k] * h2r[k];
        }
#pragma unroll
        for (int off = 16; off > 0; off >>= 1) {
            s0 += __shfl_down_sync(0xffffffffu, s0, off);
            s1 += __shfl_down_sync(0xffffffffu, s1, off);
            s2 += __shfl_down_sync(0xffffffffu, s2, off);
        }
        if (lane == 0) {
            d_C[0][n * NS + m] = s0 + 1.0f;
            d_C[1][n * NS + m] = s1 + 1.0f;
            d_C[2][n * NS + m] = s2 + 1.0f;
        }
    }
}

// ======== kP: tensor-core pair-GEMMs (3xTF32) + combine, double-buffered smem =====
#define KP_BUF_FLOATS (4 * 64 * 36)            // one buffer: 9216 floats
#define KP_SMEM_BYTES (2 * KP_BUF_FLOATS * 4)  // 73728 bytes

__global__ __launch_bounds__(512) void kP_pair(float* __restrict__ out)
{
    extern __shared__ float dsm[];

    const int tid  = threadIdx.x;
    const int lane = tid & 31;
    const int w    = tid >> 5;
    const int g    = lane >> 2;
    const int t4   = lane & 3;
    const int rt   = w & 3;
    const int cq   = w >> 2;
    const int r0 = blockIdx.y * 64, c0 = blockIdx.x * 64;

    float acc_h[2][2][4];
    float acc_c[2][2][4];
#pragma unroll
    for (int l = 0; l < 2; l++)
#pragma unroll
        for (int nt = 0; nt < 2; nt++)
#pragma unroll
            for (int q = 0; q < 4; q++) { acc_h[l][nt][q] = 0.f; acc_c[l][nt][q] = 0.f; }

    const int srow = tid >> 3;
    const int sq   = (tid & 7) * 4;

#define KP_AHI(p) (dsm + (p) * KP_BUF_FLOATS + 0 * 2304)
#define KP_ALO(p) (dsm + (p) * KP_BUF_FLOATS + 1 * 2304)
#define KP_BHI(p) (dsm + (p) * KP_BUF_FLOATS + 2 * 2304)
#define KP_BLO(p) (dsm + (p) * KP_BUF_FLOATS + 3 * 2304)

#define KP_LDG(st) {                                                           \
    const float* G = ((st) < 8) ? d_G1 : d_G2;                                 \
    const int kc = ((st) & 7) * 32;                                            \
    va = *(const float4*)&G[(r0 + srow) * D + kc + sq];                        \
    vb = *(const float4*)&G[(R + c0 + srow) * D + kc + sq];                    \
}

#define KP_MMA(p, LI) {                                                        \
    const float* pAhi = KP_AHI(p); const float* pAlo = KP_ALO(p);              \
    const float* pBhi = KP_BHI(p); const float* pBlo = KP_BLO(p);              \
    _Pragma("unroll")                                                          \
    for (int kk = 0; kk < 4; kk++) {                                           \
        const int kb = kk * 8 + t4;                                            \
        const int ar = rt * 16 + g;                                            \
        uint32_t ah0 = __float_as_uint(pAhi[ar * 36 + kb]);                    \
        uint32_t ah1 = __float_as_uint(pAhi[(ar + 8) * 36 + kb]);              \
        uint32_t ah2 = __float_as_uint(pAhi[ar * 36 + kb + 4]);                \
        uint32_t ah3 = __float_as_uint(pAhi[(ar + 8) * 36 + kb + 4]);          \
        uint32_t al0 = __float_as_uint(pAlo[ar * 36 + kb]);                    \
        uint32_t al1 = __float_as_uint(pAlo[(ar + 8) * 36 + kb]);              \
        uint32_t al2 = __float_as_uint(pAlo[ar * 36 + kb + 4]);                \
        uint32_t al3 = __float_as_uint(pAlo[(ar + 8) * 36 + kb + 4]);          \
        _Pragma("unroll")                                                      \
        for (int nt = 0; nt < 2; nt++) {                                       \
            const int nb = cq * 16 + nt * 8 + g;                               \
            uint32_t bh0 = __float_as_uint(pBhi[nb * 36 + kb]);                \
            uint32_t bh1 = __float_as_uint(pBhi[nb * 36 + kb + 4]);            \
            uint32_t bl0 = __float_as_uint(pBlo[nb * 36 + kb]);                \
            uint32_t bl1 = __float_as_uint(pBlo[nb * 36 + kb + 4]);            \
            float* chh = acc_h[LI][nt];                                        \
            float* ccr = acc_c[LI][nt];                                        \
            mma_tf32(chh[0], chh[1], chh[2], chh[3], ah0, ah1, ah2, ah3, bh0, bh1); \
            mma_tf32(ccr[0], ccr[1], ccr[2], ccr[3], ah0, ah1, ah2, ah3, bl0, bl1); \
            mma_tf32(ccr[0], ccr[1], ccr[2], ccr[3], al0, al1, al2, al3, bh0, bh1); \
        }                                                                      \
    } }

    float4 va, vb;
    KP_LDG(0)

#pragma unroll 1
    for (int st = 0; st < 16; st++) {
        const int p = st & 1;
        {
            float* pAhi = KP_AHI(p); float* pAlo = KP_ALO(p);
            float* pBhi = KP_BHI(p); float* pBlo = KP_BLO(p);
            float av[4] = {va.x, va.y, va.z, va.w};
            float bv[4] = {vb.x, vb.y, vb.z, vb.w};
            float ah[4], al[4], bh[4], bl[4];
#pragma unroll
            for (int j = 0; j < 4; j++) {
                uint32_t h = f2tf32(av[j]);
                ah[j] = __uint_as_float(h);
                al[j] = __uint_as_float(f2tf32(av[j] - ah[j]));
                h = f2tf32(bv[j]);
                bh[j] = __uint_as_float(h);
                bl[j] = __uint_as_float(f2tf32(bv[j] - bh[j]));
            }
            *(float4*)&pAhi[srow * 36 + sq] = make_float4(ah[0], ah[1], ah[2], ah[3]);
            *(float4*)&pAlo[srow * 36 + sq] = make_float4(al[0], al[1], al[2], al[3]);
            *(float4*)&pBhi[srow * 36 + sq] = make_float4(bh[0], bh[1], bh[2], bh[3]);
            *(float4*)&pBlo[srow * 36 + sq] = make_float4(bl[0], bl[1], bl[2], bl[3]);
        }
        if (st < 15) KP_LDG(st + 1)
        __syncthreads();
        if (st < 8) { KP_MMA(p, 0) } else { KP_MMA(p, 1) }
    }
#undef KP_LDG
#undef KP_MMA
#undef KP_AHI
#undef KP_ALO
#undef KP_BHI
#undef KP_BLO

    // ---- epilogue: out[n,m,a,b] = C0*P0 + C1*P1 + (a==b)*C2 ----
    const float* C0 = d_C[0];
    const float* C1 = d_C[1];
    const float* C2 = d_C[2];
#pragma unroll
    for (int nt = 0; nt < 2; nt++) {
        int col = c0 + cq * 16 + nt * 8 + 2 * t4;
        int m0 = col / 10,       bb0 = col - m0 * 10;
        int m1 = (col + 1) / 10, bb1 = (col + 1) - m1 * 10;
#pragma unroll
        for (int half = 0; half < 2; half++) {
            int row = r0 + rt * 16 + g + half * 8;
            int n = row / 10, a = row - n * 10;
            int ci0 = n * NS + m0, ci1 = n * NS + m1;
            float p00 = acc_h[0][nt][half * 2 + 0] + acc_c[0][nt][half * 2 + 0];
            float p10 = acc_h[1][nt][half * 2 + 0] + acc_c[1][nt][half * 2 + 0];
            float p01 = acc_h[0][nt][half * 2 + 1] + acc_c[0][nt][half * 2 + 1];
            float p11 = acc_h[1][nt][half * 2 + 1] + acc_c[1][nt][half * 2 + 1];
            float v0 = C0[ci0] * p00 + C1[ci0] * p10;
            float v1 = C0[ci1] * p01 + C1[ci1] * p11;
            if (a == bb0) v0 += C2[ci0];
            if (a == bb1) v1 += C2[ci1];
            out[ci0 * 100 + a * 10 + bb0] = v0;
            out[ci1 * 100 + a * 10 + bb1] = v1;
        }
    }
}

// ---------------- launcher ----------------
extern "C" void kernel_launch(void* const* d_in, const int* in_sizes, int n_in,
                              void* d_out, int out_size) {
    const float* x1 = (const float*)d_in[0];
    const float* x2 = (const float*)d_in[1];
    const float* W1 = (const float*)d_in[2];
    const float* b1 = (const float*)d_in[3];
    const float* W2 = (const float*)d_in[4];
    const float* b2 = (const float*)d_in[5];
    const float* W3 = (const float*)d_in[6];
    float* out = (float*)d_out;

    cudaFuncSetAttribute(kP_pair, cudaFuncAttributeMaxDynamicSharedMemorySize,
                         KP_SMEM_BYTES);

    k1_fwd<<<96, 512>>>(x1, x2, W1, b1, W2, b2, W3);
    kC_bwd_dots<<<320, 256>>>(x1, x2);
    kP_pair<<<dim3(10, 10), 512, KP_SMEM_BYTES>>>(out);
}